// round 15
// baseline (speedup 1.0000x reference)
#include <cuda_runtime.h>
#include <cuda_fp16.h>
#include <math.h>
#include <stdint.h>

#define BS_N 4
#define SL_N 2048
#define DM_N 1024
#define NH_N 16
#define HD_N 64
#define ROWS_N (BS_N * SL_N)          // 8192
#define QKV_COLS (3 * DM_N)           // 3072
#define LOG2E_F 1.4426950408889634f

// Scratch (no runtime allocation allowed)
__device__ __half g_qkvh[(size_t)ROWS_N * QKV_COLS];   // 50 MB
__device__ __half g_attnh[(size_t)ROWS_N * DM_N];      // 16 MB
__device__ __half g_xh[(size_t)ROWS_N * DM_N];         // 16 MB
__device__ __half g_wqkvT[(size_t)QKV_COLS * DM_N];    // w_qkv^T [N][K]
__device__ __half g_wprojT[(size_t)DM_N * DM_N];       // w_proj^T [N][K]

// ---------------------------------------------------------------------------
// helpers
// ---------------------------------------------------------------------------
__device__ __forceinline__ void mma_f16(float c[4], const unsigned a[4],
                                        const unsigned b[2]) {
    asm volatile(
        "mma.sync.aligned.m16n8k16.row.col.f32.f16.f16.f32 "
        "{%0,%1,%2,%3},{%4,%5,%6,%7},{%8,%9},{%0,%1,%2,%3};"
        : "+f"(c[0]), "+f"(c[1]), "+f"(c[2]), "+f"(c[3])
        : "r"(a[0]), "r"(a[1]), "r"(a[2]), "r"(a[3]), "r"(b[0]), "r"(b[1]));
}

// f16-accumulator variant (QK^T only; short-K, small-magnitude)
__device__ __forceinline__ void mma_f16acc(unsigned c[2], const unsigned a[4],
                                           const unsigned b[2]) {
    asm volatile(
        "mma.sync.aligned.m16n8k16.row.col.f16.f16.f16.f16 "
        "{%0,%1},{%2,%3,%4,%5},{%6,%7},{%0,%1};"
        : "+r"(c[0]), "+r"(c[1])
        : "r"(a[0]), "r"(a[1]), "r"(a[2]), "r"(a[3]), "r"(b[0]), "r"(b[1]));
}

__device__ __forceinline__ void ldsm4(unsigned r[4], uint32_t addr) {
    asm volatile("ldmatrix.sync.aligned.m8n8.x4.shared.b16 {%0,%1,%2,%3}, [%4];"
                 : "=r"(r[0]), "=r"(r[1]), "=r"(r[2]), "=r"(r[3]) : "r"(addr));
}
__device__ __forceinline__ void ldsm4t(unsigned r[4], uint32_t addr) {
    asm volatile("ldmatrix.sync.aligned.m8n8.x4.trans.shared.b16 {%0,%1,%2,%3}, [%4];"
                 : "=r"(r[0]), "=r"(r[1]), "=r"(r[2]), "=r"(r[3]) : "r"(addr));
}

__device__ __forceinline__ void cp16cg(uint32_t dst_smem, const void* src) {
    asm volatile("cp.async.cg.shared.global [%0], [%1], 16;\n"
                 :: "r"(dst_smem), "l"(src));
}
__device__ __forceinline__ void cp_commit() {
    asm volatile("cp.async.commit_group;\n");
}

__device__ __forceinline__ unsigned packh2(float a, float b) {
    __half2 h = __floats2half2_rn(a, b);
    return *reinterpret_cast<unsigned*>(&h);
}

// guaranteed single-instruction exp2 (MUFU.EX2), no library slow path
__device__ __forceinline__ float ex2(float x) {
    float r;
    asm("ex2.approx.f32 %0, %1;" : "=f"(r) : "f"(x));
    return r;
}

// ---------------------------------------------------------------------------
// Merged prologue: f2h(x) + transpose+convert of both weight matrices.
// ---------------------------------------------------------------------------
#define NBX 8192
#define NBQ 3072
#define NBP 1024

__global__ void __launch_bounds__(256) prologue_kernel(
    const float* __restrict__ x, const float* __restrict__ w_qkv,
    const float* __restrict__ w_proj, __half* __restrict__ xh,
    __half* __restrict__ wqkvT, __half* __restrict__ wprojT)
{
    __shared__ float tile[32][33];
    const int blk = blockIdx.x, tid = threadIdx.x;

    if (blk < NBX) {
        int i = (blk * 256 + tid) * 4;
        float4 v = *(const float4*)(x + i);
        *(__half2*)(xh + i)     = __floats2half2_rn(v.x, v.y);
        *(__half2*)(xh + i + 2) = __floats2half2_rn(v.z, v.w);
        return;
    }

    const float* in;
    __half* outp;
    int N, bid;
    if (blk < NBX + NBQ) { in = w_qkv;  outp = wqkvT;  N = QKV_COLS; bid = blk - NBX; }
    else                 { in = w_proj; outp = wprojT; N = DM_N;     bid = blk - NBX - NBQ; }
    const int K = DM_N;
    const int nbx = N / 32;
    const int n0 = (bid % nbx) * 32, k0 = (bid / nbx) * 32;
    const int tx = tid & 31, ty = tid >> 5;

    #pragma unroll
    for (int j = 0; j < 32; j += 8)
        tile[ty + j][tx] = in[(size_t)(k0 + ty + j) * N + n0 + tx];
    __syncthreads();
    #pragma unroll
    for (int j = 0; j < 32; j += 8)
        outp[(size_t)(n0 + ty + j) * K + k0 + tx] = __float2half(tile[tx][ty + j]);
}

// ---------------------------------------------------------------------------
// fp16 GEMM (round-10 version): block 128x128, 8 warps (2m x 4n), warp tile
// 64x32, BK=32, 4-stage cp.async pipeline, A-fragment double buffering.
// ---------------------------------------------------------------------------
#define STG_BYTES 16384               // A 8KB + B 8KB
#define GEMM_SMEM (4 * STG_BYTES)     // 65536

template <bool HALF_OUT>
__global__ void __launch_bounds__(256, 2) gemm_f16(
    const __half* __restrict__ A, const __half* __restrict__ B,
    void* __restrict__ Cv, int N, int K)
{
    extern __shared__ __align__(128) char smem[];
    const uint32_t sbase = (uint32_t)__cvta_generic_to_shared(smem);
    const int tid = threadIdx.x;
    const int warp = tid >> 5, lane = tid & 31;
    const int wm = (warp >> 2) * 64;
    const int wn = (warp & 3) * 32;
    const size_t bm = (size_t)blockIdx.y * 128;
    const size_t bn = (size_t)blockIdx.x * 128;

    float acc[4][4][4];
    #pragma unroll
    for (int mi = 0; mi < 4; mi++)
        #pragma unroll
        for (int nj = 0; nj < 4; nj++)
            #pragma unroll
            for (int r = 0; r < 4; r++) acc[mi][nj][r] = 0.f;

    const char* Ab = (const char*)(A + bm * K);
    const char* Bb = (const char*)(B + bn * K);
    const size_t rowb = (size_t)K * 2;

    auto load_chunk = [&](int kc) {
        const uint32_t st = sbase + (kc & 3) * STG_BYTES;
        #pragma unroll
        for (int i = 0; i < 2; i++) {
            int idx = tid + i * 256;
            int r = idx >> 2, c = idx & 3;
            uint32_t off = r * 64 + ((c ^ ((r >> 1) & 3)) << 4);
            cp16cg(st + off, Ab + (size_t)r * rowb + kc * 64 + c * 16);
            cp16cg(st + 8192 + off, Bb + (size_t)r * rowb + kc * 64 + c * 16);
        }
        cp_commit();
    };

    const int NC = K / 32;            // 32
    load_chunk(0); load_chunk(1);

    const int arow_l = (lane & 7) + ((lane >> 3) & 1) * 8;
    const int acol_l = lane >> 4;

    for (int kc = 0; kc < NC; kc++) {
        if (kc + 2 < NC) load_chunk(kc + 2);
        const int rem = NC - 1 - kc;
        if (rem >= 2)      asm volatile("cp.async.wait_group 2;\n" ::: "memory");
        else if (rem == 1) asm volatile("cp.async.wait_group 1;\n" ::: "memory");
        else               asm volatile("cp.async.wait_group 0;\n" ::: "memory");
        __syncthreads();

        const uint32_t sa = sbase + (kc & 3) * STG_BYTES;
        const uint32_t sb = sa + 8192;

        unsigned af[2][4][4];
        #pragma unroll
        for (int mi = 0; mi < 4; mi++) {
            int row = wm + mi * 16 + arow_l;
            int c = acol_l;
            ldsm4(af[0][mi], sa + row * 64 + ((c ^ ((row >> 1) & 3)) << 4));
        }

        #pragma unroll
        for (int s = 0; s < 2; s++) {
            unsigned bf[4][2];
            #pragma unroll
            for (int nb = 0; nb < 2; nb++) {
                unsigned r4[4];
                int row = wn + nb * 16 + arow_l;
                int c = s * 2 + acol_l;
                ldsm4(r4, sb + row * 64 + ((c ^ ((row >> 1) & 3)) << 4));
                bf[nb * 2][0] = r4[0]; bf[nb * 2][1] = r4[2];
                bf[nb * 2 + 1][0] = r4[1]; bf[nb * 2 + 1][1] = r4[3];
            }
            if (s == 0) {
                #pragma unroll
                for (int mi = 0; mi < 4; mi++) {
                    int row = wm + mi * 16 + arow_l;
                    int c = 2 + acol_l;
                    ldsm4(af[1][mi], sa + row * 64 + ((c ^ ((row >> 1) & 3)) << 4));
                }
            }
            #pragma unroll
            for (int mi = 0; mi < 4; mi++)
                #pragma unroll
                for (int nj = 0; nj < 4; nj++)
                    mma_f16(acc[mi][nj], af[s][mi], bf[nj]);
        }
    }

    const int g = lane >> 2, t = lane & 3;
    #pragma unroll
    for (int mi = 0; mi < 4; mi++) {
        #pragma unroll
        for (int nj = 0; nj < 4; nj++) {
            size_t r0 = bm + wm + mi * 16 + g;
            size_t c0 = bn + wn + nj * 8 + 2 * t;
            if (HALF_OUT) {
                __half* C = (__half*)Cv;
                *(__half2*)(C + r0 * N + c0) =
                    __floats2half2_rn(acc[mi][nj][0], acc[mi][nj][1]);
                *(__half2*)(C + (r0 + 8) * N + c0) =
                    __floats2half2_rn(acc[mi][nj][2], acc[mi][nj][3]);
            } else {
                float* C = (float*)Cv;
                *(float2*)(C + r0 * N + c0) =
                    make_float2(acc[mi][nj][0], acc[mi][nj][1]);
                *(float2*)(C + (r0 + 8) * N + c0) =
                    make_float2(acc[mi][nj][2], acc[mi][nj][3]);
            }
        }
    }
}

// ---------------------------------------------------------------------------
// Causal attention v5 (R12 structure): 64 queries/block, 4 warps x m16,
// 64-key tiles, triangular diagonal, qt reversed, f16-acc QK with log2e
// folded into Q. NEW: exp via single-instruction ex2.approx.f32 (bypasses
// any exp2f library slow path).
// ---------------------------------------------------------------------------
#define ATT_STG 16384                 // K 8KB + V 8KB

__global__ void __launch_bounds__(128) attn_f16(
    const __half* __restrict__ qkv, __half* __restrict__ outp)
{
    __shared__ __align__(128) char smem[2 * ATT_STG];
    const uint32_t sbase = (uint32_t)__cvta_generic_to_shared(smem);

    const int b = blockIdx.z, h = blockIdx.y;
    const int qt = gridDim.x - 1 - blockIdx.x;    // longest first
    const int tid = threadIdx.x;
    const int warp = tid >> 5, lane = tid & 31;
    const int g = lane >> 2, t = lane & 3;
    const int qbase = qt * 64;
    const int q0g = qbase + warp * 16 + g;

    const __half* kb = qkv + (size_t)(b * SL_N) * QKV_COLS + DM_N + h * HD_N;
    const __half* vb = kb + DM_N;

    unsigned qa[4][4];
    {
        const float qs = 0.125f * LOG2E_F;        // fold log2e into Q
        const __half2 sc = __floats2half2_rn(qs, qs);
        const __half* q0 =
            qkv + (size_t)(b * SL_N + q0g) * QKV_COLS + h * HD_N;
        const __half* q1 = q0 + (size_t)8 * QKV_COLS;
        #pragma unroll
        for (int kf = 0; kf < 4; kf++) {
            int d0 = kf * 16 + 2 * t;
            __half2 v;
            v = __hmul2(*(const __half2*)(q0 + d0), sc);
            qa[kf][0] = *(unsigned*)&v;
            v = __hmul2(*(const __half2*)(q1 + d0), sc);
            qa[kf][1] = *(unsigned*)&v;
            v = __hmul2(*(const __half2*)(q0 + d0 + 8), sc);
            qa[kf][2] = *(unsigned*)&v;
            v = __hmul2(*(const __half2*)(q1 + d0 + 8), sc);
            qa[kf][3] = *(unsigned*)&v;
        }
    }

    float o[8][4];
    #pragma unroll
    for (int j = 0; j < 8; j++)
        #pragma unroll
        for (int r = 0; r < 4; r++) o[j][r] = 0.f;
    float l0 = 0.f, l1 = 0.f;

    auto issue = [&](int kt) {
        const uint32_t st = sbase + (kt & 1) * ATT_STG;
        #pragma unroll
        for (int i = 0; i < 4; i++) {
            int idx = tid + i * 128;
            int r = idx >> 3, c = idx & 7;
            uint32_t off = r * 128 + ((c ^ (r & 7)) << 4);
            const size_t gsrc = (size_t)(kt * 64 + r) * QKV_COLS * 2 + c * 16;
            cp16cg(st + off, (const char*)kb + gsrc);
            cp16cg(st + 8192 + off, (const char*)vb + gsrc);
        }
        cp_commit();
    };

    const int nkt = qt + 1;                      // 64-key tiles
    issue(0);

    for (int kt = 0; kt < nkt; kt++) {
        asm volatile("cp.async.wait_group 0;\n" ::: "memory");
        __syncthreads();
        if (kt + 1 < nkt) issue(kt + 1);

        const uint32_t kbuf = sbase + (kt & 1) * ATT_STG;
        const uint32_t vbuf = kbuf + 8192;
        const bool last = (kt == nkt - 1);
        const int nst = last ? (warp + 1) : 4;   // triangular diagonal

        #pragma unroll
        for (int jj = 0; jj < 4; jj++) {
            if (jj >= nst) break;

            // ---- S_log2 = (Q*0.125*log2e) @ K^T, f16 accumulators ----
            unsigned ch[2][2] = {{0u, 0u}, {0u, 0u}};
            #pragma unroll
            for (int jn = 0; jn < 2; jn++) {
                int krow0 = jj * 16 + jn * 8 + (lane & 7);
                #pragma unroll
                for (int dh = 0; dh < 2; dh++) {
                    unsigned r4[4];
                    int c = dh * 4 + (lane >> 3);
                    ldsm4(r4, kbuf + krow0 * 128 + ((c ^ (krow0 & 7)) << 4));
                    unsigned b0[2] = { r4[0], r4[1] };
                    unsigned b1[2] = { r4[2], r4[3] };
                    mma_f16acc(ch[jn], qa[dh * 2], b0);
                    mma_f16acc(ch[jn], qa[dh * 2 + 1], b1);
                }
            }

            // ---- mask + exp2 -> P (transient; MUFU.EX2) ----
            float p[2][4];
            const bool masked = last && (jj == warp);
            #pragma unroll
            for (int jn = 0; jn < 2; jn++) {
                float2 s01 = __half22float2(*(__half2*)&ch[jn][0]);
                float2 s23 = __half22float2(*(__half2*)&ch[jn][1]);
                if (masked) {
                    int key0 = kt * 64 + jj * 16 + jn * 8 + 2 * t;
                    p[jn][0] = (key0     <= q0g)     ? ex2(s01.x) : 0.f;
                    p[jn][1] = (key0 + 1 <= q0g)     ? ex2(s01.y) : 0.f;
                    p[jn][2] = (key0     <= q0g + 8) ? ex2(s23.x) : 0.f;
                    p[jn][3] = (key0 + 1 <= q0g + 8) ? ex2(s23.y) : 0.f;
                } else {
                    p[jn][0] = ex2(s01.x);
                    p[jn][1] = ex2(s01.y);
                    p[jn][2] = ex2(s23.x);
                    p[jn][3] = ex2(s23.y);
                }
                l0 += p[jn][0] + p[jn][1];
                l1 += p[jn][2] + p[jn][3];
            }

            unsigned a[4] = { packh2(p[0][0], p[0][1]),
                              packh2(p[0][2], p[0][3]),
                              packh2(p[1][0], p[1][1]),
                              packh2(p[1][2], p[1][3]) };

            // ---- O += P @ V (f32 accumulators) ----
            int vrow = jj * 16 + (lane & 7) + ((lane >> 3) & 1) * 8;
            #pragma unroll
            for (int j2 = 0; j2 < 8; j2 += 2) {
                unsigned r4[4];
                int c = j2 + (lane >> 4);
                ldsm4t(r4, vbuf + vrow * 128 + ((c ^ (vrow & 7)) << 4));
                unsigned b0[2] = { r4[0], r4[1] };
                unsigned b1[2] = { r4[2], r4[3] };
                mma_f16(o[j2], a, b0);
                mma_f16(o[j2 + 1], a, b1);
            }
        }
    }

    l0 += __shfl_xor_sync(0xffffffffu, l0, 1);
    l0 += __shfl_xor_sync(0xffffffffu, l0, 2);
    l1 += __shfl_xor_sync(0xffffffffu, l1, 1);
    l1 += __shfl_xor_sync(0xffffffffu, l1, 2);
    const float inv0 = 1.0f / l0;
    const float inv1 = 1.0f / l1;

    __half* o0 = outp + (size_t)(b * SL_N + q0g) * DM_N + h * HD_N;
    __half* o1 = o0 + (size_t)8 * DM_N;
    #pragma unroll
    for (int j2 = 0; j2 < 8; j2++) {
        int c0 = j2 * 8 + 2 * t;
        *(__half2*)(o0 + c0) = __floats2half2_rn(o[j2][0] * inv0, o[j2][1] * inv0);
        *(__half2*)(o1 + c0) = __floats2half2_rn(o[j2][2] * inv1, o[j2][3] * inv1);
    }
}

// ---------------------------------------------------------------------------
extern "C" void kernel_launch(void* const* d_in, const int* in_sizes, int n_in,
                              void* d_out, int out_size)
{
    const float* x      = (const float*)d_in[0];   // (4, 2048, 1024)
    const float* w_qkv  = (const float*)d_in[1];   // (1024, 3072)
    const float* w_proj = (const float*)d_in[2];   // (1024, 1024)
    float* out          = (float*)d_out;           // (4, 2048, 1024)

    __half *qkvh, *attnh, *xh, *wqkvT, *wprojT;
    cudaGetSymbolAddress((void**)&qkvh, g_qkvh);
    cudaGetSymbolAddress((void**)&attnh, g_attnh);
    cudaGetSymbolAddress((void**)&xh, g_xh);
    cudaGetSymbolAddress((void**)&wqkvT, g_wqkvT);
    cudaGetSymbolAddress((void**)&wprojT, g_wprojT);

    cudaFuncSetAttribute(gemm_f16<true>,
                         cudaFuncAttributeMaxDynamicSharedMemorySize, GEMM_SMEM);
    cudaFuncSetAttribute(gemm_f16<false>,
                         cudaFuncAttributeMaxDynamicSharedMemorySize, GEMM_SMEM);

    // 0) Merged prologue: x->half, weights transpose->half
    prologue_kernel<<<NBX + NBQ + NBP, 256>>>(x, w_qkv, w_proj,
                                              xh, wqkvT, wprojT);

    // 1) QKV projection (fp16 mma, half epilogue feeds attention)
    gemm_f16<true><<<dim3(QKV_COLS / 128, ROWS_N / 128), 256, GEMM_SMEM>>>(
        xh, wqkvT, qkvh, QKV_COLS, DM_N);

    // 2) Causal attention (f16-acc QK, MUFU exp, f32-acc PV), half epilogue
    attn_f16<<<dim3(SL_N / 64, NH_N, BS_N), 128>>>(qkvh, attnh);

    // 3) Output projection (fp16 mma, fp32 epilogue)
    gemm_f16<false><<<dim3(DM_N / 128, ROWS_N / 128), 256, GEMM_SMEM>>>(
        attnh, wprojT, out, DM_N, DM_N);
}

// round 16
// speedup vs baseline: 1.0722x; 1.0722x over previous
#include <cuda_runtime.h>
#include <cuda_fp16.h>
#include <math.h>
#include <stdint.h>

#define BS_N 4
#define SL_N 2048
#define DM_N 1024
#define NH_N 16
#define HD_N 64
#define ROWS_N (BS_N * SL_N)          // 8192
#define QKV_COLS (3 * DM_N)           // 3072
#define LOG2E_F 1.4426950408889634f

// Scratch (no runtime allocation allowed)
__device__ __half g_qkvh[(size_t)ROWS_N * QKV_COLS];   // 50 MB
__device__ __half g_attnh[(size_t)ROWS_N * DM_N];      // 16 MB
__device__ __half g_xh[(size_t)ROWS_N * DM_N];         // 16 MB
__device__ __half g_wqkvT[(size_t)QKV_COLS * DM_N];    // w_qkv^T [N][K]
__device__ __half g_wprojT[(size_t)DM_N * DM_N];       // w_proj^T [N][K]
__device__ int    g_cnt[128];                          // per-(b,qt) head counters

// ---------------------------------------------------------------------------
// helpers
// ---------------------------------------------------------------------------
__device__ __forceinline__ void mma_f16(float c[4], const unsigned a[4],
                                        const unsigned b[2]) {
    asm volatile(
        "mma.sync.aligned.m16n8k16.row.col.f32.f16.f16.f32 "
        "{%0,%1,%2,%3},{%4,%5,%6,%7},{%8,%9},{%0,%1,%2,%3};"
        : "+f"(c[0]), "+f"(c[1]), "+f"(c[2]), "+f"(c[3])
        : "r"(a[0]), "r"(a[1]), "r"(a[2]), "r"(a[3]), "r"(b[0]), "r"(b[1]));
}

// f16-accumulator variant (QK^T only; short-K, small-magnitude)
__device__ __forceinline__ void mma_f16acc(unsigned c[2], const unsigned a[4],
                                           const unsigned b[2]) {
    asm volatile(
        "mma.sync.aligned.m16n8k16.row.col.f16.f16.f16.f16 "
        "{%0,%1},{%2,%3,%4,%5},{%6,%7},{%0,%1};"
        : "+r"(c[0]), "+r"(c[1])
        : "r"(a[0]), "r"(a[1]), "r"(a[2]), "r"(a[3]), "r"(b[0]), "r"(b[1]));
}

__device__ __forceinline__ void ldsm4(unsigned r[4], uint32_t addr) {
    asm volatile("ldmatrix.sync.aligned.m8n8.x4.shared.b16 {%0,%1,%2,%3}, [%4];"
                 : "=r"(r[0]), "=r"(r[1]), "=r"(r[2]), "=r"(r[3]) : "r"(addr));
}
__device__ __forceinline__ void ldsm4t(unsigned r[4], uint32_t addr) {
    asm volatile("ldmatrix.sync.aligned.m8n8.x4.trans.shared.b16 {%0,%1,%2,%3}, [%4];"
                 : "=r"(r[0]), "=r"(r[1]), "=r"(r[2]), "=r"(r[3]) : "r"(addr));
}

__device__ __forceinline__ void cp16cg(uint32_t dst_smem, const void* src) {
    asm volatile("cp.async.cg.shared.global [%0], [%1], 16;\n"
                 :: "r"(dst_smem), "l"(src));
}
__device__ __forceinline__ void cp_commit() {
    asm volatile("cp.async.commit_group;\n");
}

__device__ __forceinline__ unsigned packh2(float a, float b) {
    __half2 h = __floats2half2_rn(a, b);
    return *reinterpret_cast<unsigned*>(&h);
}

__device__ __forceinline__ float ex2(float x) {
    float r;
    asm("ex2.approx.f32 %0, %1;" : "=f"(r) : "f"(x));
    return r;
}

// ---------------------------------------------------------------------------
// Merged prologue: f2h(x) + transpose+convert of both weights + counter zero.
// ---------------------------------------------------------------------------
#define NBX 8192
#define NBQ 3072
#define NBP 1024

__global__ void __launch_bounds__(256) prologue_kernel(
    const float* __restrict__ x, const float* __restrict__ w_qkv,
    const float* __restrict__ w_proj, __half* __restrict__ xh,
    __half* __restrict__ wqkvT, __half* __restrict__ wprojT)
{
    __shared__ float tile[32][33];
    const int blk = blockIdx.x, tid = threadIdx.x;

    if (blk < NBX) {
        int i = (blk * 256 + tid) * 4;
        float4 v = *(const float4*)(x + i);
        *(__half2*)(xh + i)     = __floats2half2_rn(v.x, v.y);
        *(__half2*)(xh + i + 2) = __floats2half2_rn(v.z, v.w);
        return;
    }
    if (blk == NBX + NBQ + NBP) {          // zero the head counters
        if (tid < 128) g_cnt[tid] = 0;
        return;
    }

    const float* in;
    __half* outp;
    int N, bid;
    if (blk < NBX + NBQ) { in = w_qkv;  outp = wqkvT;  N = QKV_COLS; bid = blk - NBX; }
    else                 { in = w_proj; outp = wprojT; N = DM_N;     bid = blk - NBX - NBQ; }
    const int K = DM_N;
    const int nbx = N / 32;
    const int n0 = (bid % nbx) * 32, k0 = (bid / nbx) * 32;
    const int tx = tid & 31, ty = tid >> 5;

    #pragma unroll
    for (int j = 0; j < 32; j += 8)
        tile[ty + j][tx] = in[(size_t)(k0 + ty + j) * N + n0 + tx];
    __syncthreads();
    #pragma unroll
    for (int j = 0; j < 32; j += 8)
        outp[(size_t)(n0 + ty + j) * K + k0 + tx] = __float2half(tile[tx][ty + j]);
}

// ---------------------------------------------------------------------------
// fp16 GEMM (round-10 version, used for QKV only): block 128x128, 8 warps
// (2m x 4n), warp tile 64x32, BK=32, 4-stage cp.async, A-frag double buffer.
// ---------------------------------------------------------------------------
#define STG_BYTES 16384               // A 8KB + B 8KB
#define GEMM_SMEM (4 * STG_BYTES)     // 65536

__global__ void __launch_bounds__(256, 2) gemm_f16(
    const __half* __restrict__ A, const __half* __restrict__ B,
    __half* __restrict__ C, int N, int K)
{
    extern __shared__ __align__(128) char smem[];
    const uint32_t sbase = (uint32_t)__cvta_generic_to_shared(smem);
    const int tid = threadIdx.x;
    const int warp = tid >> 5, lane = tid & 31;
    const int wm = (warp >> 2) * 64;
    const int wn = (warp & 3) * 32;
    const size_t bm = (size_t)blockIdx.y * 128;
    const size_t bn = (size_t)blockIdx.x * 128;

    float acc[4][4][4];
    #pragma unroll
    for (int mi = 0; mi < 4; mi++)
        #pragma unroll
        for (int nj = 0; nj < 4; nj++)
            #pragma unroll
            for (int r = 0; r < 4; r++) acc[mi][nj][r] = 0.f;

    const char* Ab = (const char*)(A + bm * K);
    const char* Bb = (const char*)(B + bn * K);
    const size_t rowb = (size_t)K * 2;

    auto load_chunk = [&](int kc) {
        const uint32_t st = sbase + (kc & 3) * STG_BYTES;
        #pragma unroll
        for (int i = 0; i < 2; i++) {
            int idx = tid + i * 256;
            int r = idx >> 2, c = idx & 3;
            uint32_t off = r * 64 + ((c ^ ((r >> 1) & 3)) << 4);
            cp16cg(st + off, Ab + (size_t)r * rowb + kc * 64 + c * 16);
            cp16cg(st + 8192 + off, Bb + (size_t)r * rowb + kc * 64 + c * 16);
        }
        cp_commit();
    };

    const int NC = K / 32;            // 32
    load_chunk(0); load_chunk(1);

    const int arow_l = (lane & 7) + ((lane >> 3) & 1) * 8;
    const int acol_l = lane >> 4;

    for (int kc = 0; kc < NC; kc++) {
        if (kc + 2 < NC) load_chunk(kc + 2);
        const int rem = NC - 1 - kc;
        if (rem >= 2)      asm volatile("cp.async.wait_group 2;\n" ::: "memory");
        else if (rem == 1) asm volatile("cp.async.wait_group 1;\n" ::: "memory");
        else               asm volatile("cp.async.wait_group 0;\n" ::: "memory");
        __syncthreads();

        const uint32_t sa = sbase + (kc & 3) * STG_BYTES;
        const uint32_t sb = sa + 8192;

        unsigned af[2][4][4];
        #pragma unroll
        for (int mi = 0; mi < 4; mi++) {
            int row = wm + mi * 16 + arow_l;
            int c = acol_l;
            ldsm4(af[0][mi], sa + row * 64 + ((c ^ ((row >> 1) & 3)) << 4));
        }

        #pragma unroll
        for (int s = 0; s < 2; s++) {
            unsigned bf[4][2];
            #pragma unroll
            for (int nb = 0; nb < 2; nb++) {
                unsigned r4[4];
                int row = wn + nb * 16 + arow_l;
                int c = s * 2 + acol_l;
                ldsm4(r4, sb + row * 64 + ((c ^ ((row >> 1) & 3)) << 4));
                bf[nb * 2][0] = r4[0]; bf[nb * 2][1] = r4[2];
                bf[nb * 2 + 1][0] = r4[1]; bf[nb * 2 + 1][1] = r4[3];
            }
            if (s == 0) {
                #pragma unroll
                for (int mi = 0; mi < 4; mi++) {
                    int row = wm + mi * 16 + arow_l;
                    int c = 2 + acol_l;
                    ldsm4(af[1][mi], sa + row * 64 + ((c ^ ((row >> 1) & 3)) << 4));
                }
            }
            #pragma unroll
            for (int mi = 0; mi < 4; mi++)
                #pragma unroll
                for (int nj = 0; nj < 4; nj++)
                    mma_f16(acc[mi][nj], af[s][mi], bf[nj]);
        }
    }

    const int g = lane >> 2, t = lane & 3;
    #pragma unroll
    for (int mi = 0; mi < 4; mi++) {
        #pragma unroll
        for (int nj = 0; nj < 4; nj++) {
            size_t r0 = bm + wm + mi * 16 + g;
            size_t c0 = bn + wn + nj * 8 + 2 * t;
            *(__half2*)(C + r0 * N + c0) =
                __floats2half2_rn(acc[mi][nj][0], acc[mi][nj][1]);
            *(__half2*)(C + (r0 + 8) * N + c0) =
                __floats2half2_rn(acc[mi][nj][2], acc[mi][nj][3]);
        }
    }
}

// ---------------------------------------------------------------------------
// Fused attention + proj kernel. 1D grid of 3072 x 128 threads:
//   bids [0, 2048): causal attention (R12/R15 body), 64 queries per block,
//     qt-reversed (heavy first). On completion: threadfence + atomicAdd on
//     g_cnt[b*32+qt] (release).
//   bids [2048, 3072): proj 128x64 tile. Spin on the two 64-row-group
//     counters (acquire via L2 atomics), then 2-stage cp.async GEMM
//     C[128,64] = attnh[128,1024] @ wprojT[64,1024]^T, fp32 epilogue.
// Dispatch is bid-ordered, so proj blocks become resident only after all
// attention blocks are dispatched -> spin cannot deadlock.
// cp.async.cg reads are L2-only: no stale-L1 hazard on attnh.
// ---------------------------------------------------------------------------
#define ATT_BLKS 2048
#define PROJ_BLKS 1024
#define ATT_STG 16384                 // K 8KB + V 8KB
#define PROJ_STG 12288                // A 8KB + B 4KB
#define FUSED_SMEM (2 * ATT_STG)      // 32768 (proj uses 24KB of it)

__global__ void __launch_bounds__(128) fused_attn_proj(
    const __half* __restrict__ qkv, __half* __restrict__ attnh,
    const __half* __restrict__ wprojT, float* __restrict__ outp)
{
    extern __shared__ __align__(128) char smem[];
    const uint32_t sbase = (uint32_t)__cvta_generic_to_shared(smem);
    const int bid = blockIdx.x;
    const int tid = threadIdx.x;
    const int warp = tid >> 5, lane = tid & 31;
    const int g = lane >> 2, t = lane & 3;

    if (bid < ATT_BLKS) {
        // =================== attention ===================
        const int b = bid >> 9;                  // 512 blocks per batch
        const int h = (bid >> 5) & 15;
        const int qt = 31 - (bid & 31);          // heavy first
        const int qbase = qt * 64;
        const int q0g = qbase + warp * 16 + g;

        const __half* kb = qkv + (size_t)(b * SL_N) * QKV_COLS + DM_N + h * HD_N;
        const __half* vb = kb + DM_N;

        unsigned qa[4][4];
        {
            const float qs = 0.125f * LOG2E_F;
            const __half2 sc = __floats2half2_rn(qs, qs);
            const __half* q0 =
                qkv + (size_t)(b * SL_N + q0g) * QKV_COLS + h * HD_N;
            const __half* q1 = q0 + (size_t)8 * QKV_COLS;
            #pragma unroll
            for (int kf = 0; kf < 4; kf++) {
                int d0 = kf * 16 + 2 * t;
                __half2 v;
                v = __hmul2(*(const __half2*)(q0 + d0), sc);
                qa[kf][0] = *(unsigned*)&v;
                v = __hmul2(*(const __half2*)(q1 + d0), sc);
                qa[kf][1] = *(unsigned*)&v;
                v = __hmul2(*(const __half2*)(q0 + d0 + 8), sc);
                qa[kf][2] = *(unsigned*)&v;
                v = __hmul2(*(const __half2*)(q1 + d0 + 8), sc);
                qa[kf][3] = *(unsigned*)&v;
            }
        }

        float o[8][4];
        #pragma unroll
        for (int j = 0; j < 8; j++)
            #pragma unroll
            for (int r = 0; r < 4; r++) o[j][r] = 0.f;
        float l0 = 0.f, l1 = 0.f;

        auto issue = [&](int kt) {
            const uint32_t st = sbase + (kt & 1) * ATT_STG;
            #pragma unroll
            for (int i = 0; i < 4; i++) {
                int idx = tid + i * 128;
                int r = idx >> 3, c = idx & 7;
                uint32_t off = r * 128 + ((c ^ (r & 7)) << 4);
                const size_t gsrc = (size_t)(kt * 64 + r) * QKV_COLS * 2 + c * 16;
                cp16cg(st + off, (const char*)kb + gsrc);
                cp16cg(st + 8192 + off, (const char*)vb + gsrc);
            }
            cp_commit();
        };

        const int nkt = qt + 1;
        issue(0);

        for (int kt = 0; kt < nkt; kt++) {
            asm volatile("cp.async.wait_group 0;\n" ::: "memory");
            __syncthreads();
            if (kt + 1 < nkt) issue(kt + 1);

            const uint32_t kbuf = sbase + (kt & 1) * ATT_STG;
            const uint32_t vbuf = kbuf + 8192;
            const bool last = (kt == nkt - 1);
            const int nst = last ? (warp + 1) : 4;

            #pragma unroll
            for (int jj = 0; jj < 4; jj++) {
                if (jj >= nst) break;

                unsigned ch[2][2] = {{0u, 0u}, {0u, 0u}};
                #pragma unroll
                for (int jn = 0; jn < 2; jn++) {
                    int krow0 = jj * 16 + jn * 8 + (lane & 7);
                    #pragma unroll
                    for (int dh = 0; dh < 2; dh++) {
                        unsigned r4[4];
                        int c = dh * 4 + (lane >> 3);
                        ldsm4(r4, kbuf + krow0 * 128 + ((c ^ (krow0 & 7)) << 4));
                        unsigned b0[2] = { r4[0], r4[1] };
                        unsigned b1[2] = { r4[2], r4[3] };
                        mma_f16acc(ch[jn], qa[dh * 2], b0);
                        mma_f16acc(ch[jn], qa[dh * 2 + 1], b1);
                    }
                }

                float p[2][4];
                const bool masked = last && (jj == warp);
                #pragma unroll
                for (int jn = 0; jn < 2; jn++) {
                    float2 s01 = __half22float2(*(__half2*)&ch[jn][0]);
                    float2 s23 = __half22float2(*(__half2*)&ch[jn][1]);
                    if (masked) {
                        int key0 = kt * 64 + jj * 16 + jn * 8 + 2 * t;
                        p[jn][0] = (key0     <= q0g)     ? ex2(s01.x) : 0.f;
                        p[jn][1] = (key0 + 1 <= q0g)     ? ex2(s01.y) : 0.f;
                        p[jn][2] = (key0     <= q0g + 8) ? ex2(s23.x) : 0.f;
                        p[jn][3] = (key0 + 1 <= q0g + 8) ? ex2(s23.y) : 0.f;
                    } else {
                        p[jn][0] = ex2(s01.x);
                        p[jn][1] = ex2(s01.y);
                        p[jn][2] = ex2(s23.x);
                        p[jn][3] = ex2(s23.y);
                    }
                    l0 += p[jn][0] + p[jn][1];
                    l1 += p[jn][2] + p[jn][3];
                }

                unsigned a[4] = { packh2(p[0][0], p[0][1]),
                                  packh2(p[0][2], p[0][3]),
                                  packh2(p[1][0], p[1][1]),
                                  packh2(p[1][2], p[1][3]) };

                int vrow = jj * 16 + (lane & 7) + ((lane >> 3) & 1) * 8;
                #pragma unroll
                for (int j2 = 0; j2 < 8; j2 += 2) {
                    unsigned r4[4];
                    int c = j2 + (lane >> 4);
                    ldsm4t(r4, vbuf + vrow * 128 + ((c ^ (vrow & 7)) << 4));
                    unsigned b0[2] = { r4[0], r4[1] };
                    unsigned b1[2] = { r4[2], r4[3] };
                    mma_f16(o[j2], a, b0);
                    mma_f16(o[j2 + 1], a, b1);
                }
            }
        }

        l0 += __shfl_xor_sync(0xffffffffu, l0, 1);
        l0 += __shfl_xor_sync(0xffffffffu, l0, 2);
        l1 += __shfl_xor_sync(0xffffffffu, l1, 1);
        l1 += __shfl_xor_sync(0xffffffffu, l1, 2);
        const float inv0 = 1.0f / l0;
        const float inv1 = 1.0f / l1;

        __half* o0 = attnh + (size_t)(b * SL_N + q0g) * DM_N + h * HD_N;
        __half* o1 = o0 + (size_t)8 * DM_N;
        #pragma unroll
        for (int j2 = 0; j2 < 8; j2++) {
            int c0 = j2 * 8 + 2 * t;
            *(__half2*)(o0 + c0) = __floats2half2_rn(o[j2][0] * inv0, o[j2][1] * inv0);
            *(__half2*)(o1 + c0) = __floats2half2_rn(o[j2][2] * inv1, o[j2][3] * inv1);
        }

        // release: make this head's 64-row slice visible, then count it
        __threadfence();
        __syncthreads();
        if (tid == 0) atomicAdd(&g_cnt[b * 32 + qt], 1);

    } else {
        // =================== proj (128x64 tile) ===================
        const int pid = bid - ATT_BLKS;          // 0..1023
        const int m0 = (pid >> 4) * 128;         // 64 m-tiles
        const int n0 = (pid & 15) * 64;          // 16 n-tiles
        const int ga = m0 >> 6;                  // two 64-row groups
        const int gb = ga + 1;

        if (tid == 0) {
            while (atomicAdd(&g_cnt[ga], 0) < 16) __nanosleep(128);
            while (atomicAdd(&g_cnt[gb], 0) < 16) __nanosleep(128);
        }
        __syncthreads();

        const int wm = (warp & 1) * 64;
        const int wn = (warp >> 1) * 32;

        float acc[4][4][4];
        #pragma unroll
        for (int mi = 0; mi < 4; mi++)
            #pragma unroll
            for (int nj = 0; nj < 4; nj++)
                #pragma unroll
                for (int r = 0; r < 4; r++) acc[mi][nj][r] = 0.f;

        const char* Ab = (const char*)(attnh + (size_t)m0 * DM_N);
        const char* Bb = (const char*)(wprojT + (size_t)n0 * DM_N);
        const size_t rowb = (size_t)DM_N * 2;

        auto load_chunk = [&](int kc) {
            const uint32_t st = sbase + (kc & 1) * PROJ_STG;
            #pragma unroll
            for (int i = 0; i < 4; i++) {        // A: 128 rows x 4 chunks
                int idx = tid + i * 128;
                int r = idx >> 2, c = idx & 3;
                uint32_t off = r * 64 + ((c ^ ((r >> 1) & 3)) << 4);
                cp16cg(st + off, Ab + (size_t)r * rowb + kc * 64 + c * 16);
            }
            #pragma unroll
            for (int i = 0; i < 2; i++) {        // B: 64 rows x 4 chunks
                int idx = tid + i * 128;
                int r = idx >> 2, c = idx & 3;
                uint32_t off = r * 64 + ((c ^ ((r >> 1) & 3)) << 4);
                cp16cg(st + 8192 + off, Bb + (size_t)r * rowb + kc * 64 + c * 16);
            }
            cp_commit();
        };

        const int NC = DM_N / 32;                // 32
        load_chunk(0);

        for (int kc = 0; kc < NC; kc++) {
            asm volatile("cp.async.wait_group 0;\n" ::: "memory");
            __syncthreads();
            if (kc + 1 < NC) load_chunk(kc + 1);

            const uint32_t sa = sbase + (kc & 1) * PROJ_STG;
            const uint32_t sb = sa + 8192;
            #pragma unroll
            for (int s = 0; s < 2; s++) {
                unsigned af[4][4];
                #pragma unroll
                for (int mi = 0; mi < 4; mi++) {
                    int row = wm + mi * 16 + (lane & 7) + ((lane >> 3) & 1) * 8;
                    int c = s * 2 + (lane >> 4);
                    ldsm4(af[mi], sa + row * 64 + ((c ^ ((row >> 1) & 3)) << 4));
                }
                unsigned bf[4][2];
                #pragma unroll
                for (int nb = 0; nb < 2; nb++) {
                    unsigned r4[4];
                    int row = wn + nb * 16 + (lane & 7) + ((lane >> 3) & 1) * 8;
                    int c = s * 2 + (lane >> 4);
                    ldsm4(r4, sb + row * 64 + ((c ^ ((row >> 1) & 3)) << 4));
                    bf[nb * 2][0] = r4[0]; bf[nb * 2][1] = r4[2];
                    bf[nb * 2 + 1][0] = r4[1]; bf[nb * 2 + 1][1] = r4[3];
                }
                #pragma unroll
                for (int mi = 0; mi < 4; mi++)
                    #pragma unroll
                    for (int nj = 0; nj < 4; nj++)
                        mma_f16(acc[mi][nj], af[mi], bf[nj]);
            }
        }

        #pragma unroll
        for (int mi = 0; mi < 4; mi++) {
            #pragma unroll
            for (int nj = 0; nj < 4; nj++) {
                size_t r0 = (size_t)m0 + wm + mi * 16 + g;
                size_t c0 = (size_t)n0 + wn + nj * 8 + 2 * t;
                *(float2*)(outp + r0 * DM_N + c0) =
                    make_float2(acc[mi][nj][0], acc[mi][nj][1]);
                *(float2*)(outp + (r0 + 8) * DM_N + c0) =
                    make_float2(acc[mi][nj][2], acc[mi][nj][3]);
            }
        }
    }
}

// ---------------------------------------------------------------------------
extern "C" void kernel_launch(void* const* d_in, const int* in_sizes, int n_in,
                              void* d_out, int out_size)
{
    const float* x      = (const float*)d_in[0];   // (4, 2048, 1024)
    const float* w_qkv  = (const float*)d_in[1];   // (1024, 3072)
    const float* w_proj = (const float*)d_in[2];   // (1024, 1024)
    float* out          = (float*)d_out;           // (4, 2048, 1024)

    __half *qkvh, *attnh, *xh, *wqkvT, *wprojT;
    cudaGetSymbolAddress((void**)&qkvh, g_qkvh);
    cudaGetSymbolAddress((void**)&attnh, g_attnh);
    cudaGetSymbolAddress((void**)&xh, g_xh);
    cudaGetSymbolAddress((void**)&wqkvT, g_wqkvT);
    cudaGetSymbolAddress((void**)&wprojT, g_wprojT);

    cudaFuncSetAttribute(gemm_f16,
                         cudaFuncAttributeMaxDynamicSharedMemorySize, GEMM_SMEM);
    cudaFuncSetAttribute(fused_attn_proj,
                         cudaFuncAttributeMaxDynamicSharedMemorySize, FUSED_SMEM);

    // 0) Prologue: x->half, weights transpose->half, zero counters
    prologue_kernel<<<NBX + NBQ + NBP + 1, 256>>>(x, w_qkv, w_proj,
                                                  xh, wqkvT, wprojT);

    // 1) QKV projection (fp16 mma, half epilogue feeds attention)
    gemm_f16<<<dim3(QKV_COLS / 128, ROWS_N / 128), 256, GEMM_SMEM>>>(
        xh, wqkvT, qkvh, QKV_COLS, DM_N);

    // 2+3) Fused: causal attention + dataflow-ordered proj
    fused_attn_proj<<<ATT_BLKS + PROJ_BLKS, 128, FUSED_SMEM>>>(
        qkvh, attnh, wprojT, out);
}

// round 17
// speedup vs baseline: 1.1072x; 1.0326x over previous
#include <cuda_runtime.h>
#include <cuda_fp16.h>
#include <math.h>
#include <stdint.h>

#define BS_N 4
#define SL_N 2048
#define DM_N 1024
#define NH_N 16
#define HD_N 64
#define ROWS_N (BS_N * SL_N)          // 8192
#define QKV_COLS (3 * DM_N)           // 3072
#define LOG2E_F 1.4426950408889634f

// Scratch (no runtime allocation allowed)
__device__ __half g_qkvh[(size_t)ROWS_N * QKV_COLS];   // 50 MB
__device__ __half g_attnh[(size_t)ROWS_N * DM_N];      // 16 MB
__device__ __half g_xh[(size_t)ROWS_N * DM_N];         // 16 MB
__device__ __half g_wqkvT[(size_t)QKV_COLS * DM_N];    // w_qkv^T [N][K]
__device__ __half g_wprojT[(size_t)DM_N * DM_N];       // w_proj^T [N][K]
__device__ int    g_qcnt[64];                          // per-128-row qkv tiles
__device__ int    g_acnt[64];                          // per-128-row attn groups

// ---------------------------------------------------------------------------
// helpers
// ---------------------------------------------------------------------------
__device__ __forceinline__ void mma_f16(float c[4], const unsigned a[4],
                                        const unsigned b[2]) {
    asm volatile(
        "mma.sync.aligned.m16n8k16.row.col.f32.f16.f16.f32 "
        "{%0,%1,%2,%3},{%4,%5,%6,%7},{%8,%9},{%0,%1,%2,%3};"
        : "+f"(c[0]), "+f"(c[1]), "+f"(c[2]), "+f"(c[3])
        : "r"(a[0]), "r"(a[1]), "r"(a[2]), "r"(a[3]), "r"(b[0]), "r"(b[1]));
}

__device__ __forceinline__ void mma_f16acc(unsigned c[2], const unsigned a[4],
                                           const unsigned b[2]) {
    asm volatile(
        "mma.sync.aligned.m16n8k16.row.col.f16.f16.f16.f16 "
        "{%0,%1},{%2,%3,%4,%5},{%6,%7},{%0,%1};"
        : "+r"(c[0]), "+r"(c[1])
        : "r"(a[0]), "r"(a[1]), "r"(a[2]), "r"(a[3]), "r"(b[0]), "r"(b[1]));
}

__device__ __forceinline__ void ldsm4(unsigned r[4], uint32_t addr) {
    asm volatile("ldmatrix.sync.aligned.m8n8.x4.shared.b16 {%0,%1,%2,%3}, [%4];"
                 : "=r"(r[0]), "=r"(r[1]), "=r"(r[2]), "=r"(r[3]) : "r"(addr));
}
__device__ __forceinline__ void ldsm4t(unsigned r[4], uint32_t addr) {
    asm volatile("ldmatrix.sync.aligned.m8n8.x4.trans.shared.b16 {%0,%1,%2,%3}, [%4];"
                 : "=r"(r[0]), "=r"(r[1]), "=r"(r[2]), "=r"(r[3]) : "r"(addr));
}

__device__ __forceinline__ void cp16cg(uint32_t dst_smem, const void* src) {
    asm volatile("cp.async.cg.shared.global [%0], [%1], 16;\n"
                 :: "r"(dst_smem), "l"(src));
}
__device__ __forceinline__ void cp_commit() {
    asm volatile("cp.async.commit_group;\n");
}

__device__ __forceinline__ unsigned packh2(float a, float b) {
    __half2 h = __floats2half2_rn(a, b);
    return *reinterpret_cast<unsigned*>(&h);
}

__device__ __forceinline__ float ex2(float x) {
    float r;
    asm("ex2.approx.f32 %0, %1;" : "=f"(r) : "f"(x));
    return r;
}

// ---------------------------------------------------------------------------
// Merged prologue: f2h(x) + transpose+convert of both weights + counter zero.
// ---------------------------------------------------------------------------
#define NBX 8192
#define NBQ 3072
#define NBP 1024

__global__ void __launch_bounds__(256) prologue_kernel(
    const float* __restrict__ x, const float* __restrict__ w_qkv,
    const float* __restrict__ w_proj, __half* __restrict__ xh,
    __half* __restrict__ wqkvT, __half* __restrict__ wprojT)
{
    __shared__ float tile[32][33];
    const int blk = blockIdx.x, tid = threadIdx.x;

    if (blk < NBX) {
        int i = (blk * 256 + tid) * 4;
        float4 v = *(const float4*)(x + i);
        *(__half2*)(xh + i)     = __floats2half2_rn(v.x, v.y);
        *(__half2*)(xh + i + 2) = __floats2half2_rn(v.z, v.w);
        return;
    }
    if (blk == NBX + NBQ + NBP) {          // zero the stage counters
        if (tid < 64) g_qcnt[tid] = 0;
        else if (tid < 128) g_acnt[tid - 64] = 0;
        return;
    }

    const float* in;
    __half* outp;
    int N, bid;
    if (blk < NBX + NBQ) { in = w_qkv;  outp = wqkvT;  N = QKV_COLS; bid = blk - NBX; }
    else                 { in = w_proj; outp = wprojT; N = DM_N;     bid = blk - NBX - NBQ; }
    const int K = DM_N;
    const int nbx = N / 32;
    const int n0 = (bid % nbx) * 32, k0 = (bid / nbx) * 32;
    const int tx = tid & 31, ty = tid >> 5;

    #pragma unroll
    for (int j = 0; j < 32; j += 8)
        tile[ty + j][tx] = in[(size_t)(k0 + ty + j) * N + n0 + tx];
    __syncthreads();
    #pragma unroll
    for (int j = 0; j < 32; j += 8)
        outp[(size_t)(n0 + ty + j) * K + k0 + tx] = __float2half(tile[tx][ty + j]);
}

// ---------------------------------------------------------------------------
// MEGA kernel: QKV gemm -> attention -> proj, one launch, 256 threads/block.
//   bids [0, 1536):     QKV 128x128 tiles (m-major), signal g_qcnt[m] (24/tile)
//   bids [1536, 2560):  attention 128 queries/block (8 warps x m16),
//                       b asc / qt desc, spin on g_qcnt, signal g_acnt
//   bids [2560, 3072):  proj 128x128 tiles, spin on g_acnt[m] == 16
// Dispatch is bid-ordered -> monotone dependency pipeline, deadlock-free.
// Release: STG + threadfence + atomicAdd. Acquire: L2 atomic poll; consumer
// reads via cp.async.cg (L2) or first-touch LDG (never cached pre-release).
// ---------------------------------------------------------------------------
#define NQKV 1536
#define NATT 1024
#define NPROJ 512
#define STG_BYTES 16384               // gemm stage: A 8KB + B 8KB
#define MEGA_SMEM (4 * STG_BYTES)     // 65536
#define ATT_STG 16384                 // attn buffer: K 8KB + V 8KB (2 bufs = 32KB)

// shared gemm body (QKV and proj): C[128,128] tile at (bm, bn), K=1024
template <bool HALF_OUT>
__device__ __forceinline__ void gemm_body(
    uint32_t sbase, int tid, const __half* __restrict__ A,
    const __half* __restrict__ B, void* __restrict__ Cv,
    size_t bm, size_t bn, int N)
{
    const int warp = tid >> 5, lane = tid & 31;
    const int wm = (warp >> 2) * 64;
    const int wn = (warp & 3) * 32;
    const int K = DM_N;

    float acc[4][4][4];
    #pragma unroll
    for (int mi = 0; mi < 4; mi++)
        #pragma unroll
        for (int nj = 0; nj < 4; nj++)
            #pragma unroll
            for (int r = 0; r < 4; r++) acc[mi][nj][r] = 0.f;

    const char* Ab = (const char*)(A + bm * K);
    const char* Bb = (const char*)(B + bn * K);
    const size_t rowb = (size_t)K * 2;

    auto load_chunk = [&](int kc) {
        const uint32_t st = sbase + (kc & 3) * STG_BYTES;
        #pragma unroll
        for (int i = 0; i < 2; i++) {
            int idx = tid + i * 256;
            int r = idx >> 2, c = idx & 3;
            uint32_t off = r * 64 + ((c ^ ((r >> 1) & 3)) << 4);
            cp16cg(st + off, Ab + (size_t)r * rowb + kc * 64 + c * 16);
            cp16cg(st + 8192 + off, Bb + (size_t)r * rowb + kc * 64 + c * 16);
        }
        cp_commit();
    };

    const int NC = K / 32;            // 32
    load_chunk(0); load_chunk(1);

    const int arow_l = (lane & 7) + ((lane >> 3) & 1) * 8;
    const int acol_l = lane >> 4;

    for (int kc = 0; kc < NC; kc++) {
        if (kc + 2 < NC) load_chunk(kc + 2);
        const int rem = NC - 1 - kc;
        if (rem >= 2)      asm volatile("cp.async.wait_group 2;\n" ::: "memory");
        else if (rem == 1) asm volatile("cp.async.wait_group 1;\n" ::: "memory");
        else               asm volatile("cp.async.wait_group 0;\n" ::: "memory");
        __syncthreads();

        const uint32_t sa = sbase + (kc & 3) * STG_BYTES;
        const uint32_t sb = sa + 8192;

        unsigned af[2][4][4];
        #pragma unroll
        for (int mi = 0; mi < 4; mi++) {
            int row = wm + mi * 16 + arow_l;
            int c = acol_l;
            ldsm4(af[0][mi], sa + row * 64 + ((c ^ ((row >> 1) & 3)) << 4));
        }

        #pragma unroll
        for (int s = 0; s < 2; s++) {
            unsigned bf[4][2];
            #pragma unroll
            for (int nb = 0; nb < 2; nb++) {
                unsigned r4[4];
                int row = wn + nb * 16 + arow_l;
                int c = s * 2 + acol_l;
                ldsm4(r4, sb + row * 64 + ((c ^ ((row >> 1) & 3)) << 4));
                bf[nb * 2][0] = r4[0]; bf[nb * 2][1] = r4[2];
                bf[nb * 2 + 1][0] = r4[1]; bf[nb * 2 + 1][1] = r4[3];
            }
            if (s == 0) {
                #pragma unroll
                for (int mi = 0; mi < 4; mi++) {
                    int row = wm + mi * 16 + arow_l;
                    int c = 2 + acol_l;
                    ldsm4(af[1][mi], sa + row * 64 + ((c ^ ((row >> 1) & 3)) << 4));
                }
            }
            #pragma unroll
            for (int mi = 0; mi < 4; mi++)
                #pragma unroll
                for (int nj = 0; nj < 4; nj++)
                    mma_f16(acc[mi][nj], af[s][mi], bf[nj]);
        }
    }

    const int g = lane >> 2, t = lane & 3;
    #pragma unroll
    for (int mi = 0; mi < 4; mi++) {
        #pragma unroll
        for (int nj = 0; nj < 4; nj++) {
            size_t r0 = bm + wm + mi * 16 + g;
            size_t c0 = bn + wn + nj * 8 + 2 * t;
            if (HALF_OUT) {
                __half* C = (__half*)Cv;
                *(__half2*)(C + r0 * N + c0) =
                    __floats2half2_rn(acc[mi][nj][0], acc[mi][nj][1]);
                *(__half2*)(C + (r0 + 8) * N + c0) =
                    __floats2half2_rn(acc[mi][nj][2], acc[mi][nj][3]);
            } else {
                float* C = (float*)Cv;
                *(float2*)(C + r0 * N + c0) =
                    make_float2(acc[mi][nj][0], acc[mi][nj][1]);
                *(float2*)(C + (r0 + 8) * N + c0) =
                    make_float2(acc[mi][nj][2], acc[mi][nj][3]);
            }
        }
    }
}

__global__ void __launch_bounds__(256, 2) mega_kernel(
    const __half* __restrict__ xh, const __half* __restrict__ wqkvT,
    const __half* __restrict__ wprojT, __half* __restrict__ qkvh,
    __half* __restrict__ attnh, float* __restrict__ outp)
{
    extern __shared__ __align__(128) char smem[];
    const uint32_t sbase = (uint32_t)__cvta_generic_to_shared(smem);
    const int bid = blockIdx.x;
    const int tid = threadIdx.x;

    if (bid < NQKV) {
        // ================= stage 1: QKV gemm =================
        const int m = bid / 24;                 // m-major: batch 0 first
        const int n = bid % 24;
        gemm_body<true>(sbase, tid, xh, wqkvT, qkvh,
                        (size_t)m * 128, (size_t)n * 128, QKV_COLS);
        __threadfence();
        __syncthreads();
        if (tid == 0) atomicAdd(&g_qcnt[m], 1);

    } else if (bid < NQKV + NATT) {
        // ================= stage 2: attention (128 queries) =================
        const int a = bid - NQKV;
        const int b = a >> 8;                   // batch ascending
        const int r = a & 255;
        const int h = r & 15;
        const int qt = 15 - (r >> 4);           // heavy first
        const int warp = tid >> 5, lane = tid & 31;
        const int g = lane >> 2, t = lane & 3;
        const int qbase = qt * 128;
        const int wq = qbase + warp * 16;
        const int q0g = wq + g;

        // acquire: QKV row-tiles b*16 .. b*16+qt must be complete
        if (tid == 0) {
            #pragma unroll 1
            for (int i = 0; i <= qt; i++)
                while (atomicAdd(&g_qcnt[b * 16 + i], 0) < 24) __nanosleep(64);
        }
        __syncthreads();

        const __half* kb = qkvh + (size_t)(b * SL_N) * QKV_COLS + DM_N + h * HD_N;
        const __half* vb = kb + DM_N;

        unsigned qa[4][4];
        {
            const float qs = 0.125f * LOG2E_F;
            const __half2 sc = __floats2half2_rn(qs, qs);
            const __half* q0 =
                qkvh + (size_t)(b * SL_N + q0g) * QKV_COLS + h * HD_N;
            const __half* q1 = q0 + (size_t)8 * QKV_COLS;
            #pragma unroll
            for (int kf = 0; kf < 4; kf++) {
                int d0 = kf * 16 + 2 * t;
                __half2 v;
                v = __hmul2(*(const __half2*)(q0 + d0), sc);
                qa[kf][0] = *(unsigned*)&v;
                v = __hmul2(*(const __half2*)(q1 + d0), sc);
                qa[kf][1] = *(unsigned*)&v;
                v = __hmul2(*(const __half2*)(q0 + d0 + 8), sc);
                qa[kf][2] = *(unsigned*)&v;
                v = __hmul2(*(const __half2*)(q1 + d0 + 8), sc);
                qa[kf][3] = *(unsigned*)&v;
            }
        }

        float o[8][4];
        #pragma unroll
        for (int j = 0; j < 8; j++)
            #pragma unroll
            for (int rr = 0; rr < 4; rr++) o[j][rr] = 0.f;
        float l0 = 0.f, l1 = 0.f;

        auto issue = [&](int kt) {
            const uint32_t st = sbase + (kt & 1) * ATT_STG;
            #pragma unroll
            for (int i = 0; i < 2; i++) {
                int idx = tid + i * 256;
                int rr = idx >> 3, c = idx & 7;
                uint32_t off = rr * 128 + ((c ^ (rr & 7)) << 4);
                const size_t gsrc = (size_t)(kt * 64 + rr) * QKV_COLS * 2 + c * 16;
                cp16cg(st + off, (const char*)kb + gsrc);
                cp16cg(st + 8192 + off, (const char*)vb + gsrc);
            }
            cp_commit();
        };

        const int nkt = 2 * qt + 2;             // 64-key tiles over qbase+128
        issue(0);

        for (int kt = 0; kt < nkt; kt++) {
            asm volatile("cp.async.wait_group 0;\n" ::: "memory");
            __syncthreads();
            if (kt + 1 < nkt) issue(kt + 1);

            const uint32_t kbuf = sbase + (kt & 1) * ATT_STG;
            const uint32_t vbuf = kbuf + 8192;
            // triangular per-warp step count
            const int rel = wq + 15 - kt * 64;
            const int nst = rel < 0 ? 0 : (rel >= 48 ? 4 : (rel >> 4) + 1);

            #pragma unroll
            for (int jj = 0; jj < 4; jj++) {
                if (jj >= nst) break;

                unsigned ch[2][2] = {{0u, 0u}, {0u, 0u}};
                #pragma unroll
                for (int jn = 0; jn < 2; jn++) {
                    int krow0 = jj * 16 + jn * 8 + (lane & 7);
                    #pragma unroll
                    for (int dh = 0; dh < 2; dh++) {
                        unsigned r4[4];
                        int c = dh * 4 + (lane >> 3);
                        ldsm4(r4, kbuf + krow0 * 128 + ((c ^ (krow0 & 7)) << 4));
                        unsigned b0[2] = { r4[0], r4[1] };
                        unsigned b1[2] = { r4[2], r4[3] };
                        mma_f16acc(ch[jn], qa[dh * 2], b0);
                        mma_f16acc(ch[jn], qa[dh * 2 + 1], b1);
                    }
                }

                float p[2][4];
                const bool masked = (kt * 64 + jj * 16 + 15) > wq;
                #pragma unroll
                for (int jn = 0; jn < 2; jn++) {
                    float2 s01 = __half22float2(*(__half2*)&ch[jn][0]);
                    float2 s23 = __half22float2(*(__half2*)&ch[jn][1]);
                    if (masked) {
                        int key0 = kt * 64 + jj * 16 + jn * 8 + 2 * t;
                        p[jn][0] = (key0     <= q0g)     ? ex2(s01.x) : 0.f;
                        p[jn][1] = (key0 + 1 <= q0g)     ? ex2(s01.y) : 0.f;
                        p[jn][2] = (key0     <= q0g + 8) ? ex2(s23.x) : 0.f;
                        p[jn][3] = (key0 + 1 <= q0g + 8) ? ex2(s23.y) : 0.f;
                    } else {
                        p[jn][0] = ex2(s01.x);
                        p[jn][1] = ex2(s01.y);
                        p[jn][2] = ex2(s23.x);
                        p[jn][3] = ex2(s23.y);
                    }
                    l0 += p[jn][0] + p[jn][1];
                    l1 += p[jn][2] + p[jn][3];
                }

                unsigned a4[4] = { packh2(p[0][0], p[0][1]),
                                   packh2(p[0][2], p[0][3]),
                                   packh2(p[1][0], p[1][1]),
                                   packh2(p[1][2], p[1][3]) };

                int vrow = jj * 16 + (lane & 7) + ((lane >> 3) & 1) * 8;
                #pragma unroll
                for (int j2 = 0; j2 < 8; j2 += 2) {
                    unsigned r4[4];
                    int c = j2 + (lane >> 4);
                    ldsm4t(r4, vbuf + vrow * 128 + ((c ^ (vrow & 7)) << 4));
                    unsigned b0[2] = { r4[0], r4[1] };
                    unsigned b1[2] = { r4[2], r4[3] };
                    mma_f16(o[j2], a4, b0);
                    mma_f16(o[j2 + 1], a4, b1);
                }
            }
        }

        l0 += __shfl_xor_sync(0xffffffffu, l0, 1);
        l0 += __shfl_xor_sync(0xffffffffu, l0, 2);
        l1 += __shfl_xor_sync(0xffffffffu, l1, 1);
        l1 += __shfl_xor_sync(0xffffffffu, l1, 2);
        const float inv0 = 1.0f / l0;
        const float inv1 = 1.0f / l1;

        __half* o0 = attnh + (size_t)(b * SL_N + q0g) * DM_N + h * HD_N;
        __half* o1 = o0 + (size_t)8 * DM_N;
        #pragma unroll
        for (int j2 = 0; j2 < 8; j2++) {
            int c0 = j2 * 8 + 2 * t;
            *(__half2*)(o0 + c0) = __floats2half2_rn(o[j2][0] * inv0, o[j2][1] * inv0);
            *(__half2*)(o1 + c0) = __floats2half2_rn(o[j2][2] * inv1, o[j2][3] * inv1);
        }

        __threadfence();
        __syncthreads();
        if (tid == 0) atomicAdd(&g_acnt[b * 16 + qt], 1);

    } else {
        // ================= stage 3: proj =================
        const int pid = bid - NQKV - NATT;      // 0..511
        const int m = pid >> 3;                 // 64 m-tiles (=attn groups)
        const int n0 = (pid & 7) * 128;
        if (tid == 0) {
            while (atomicAdd(&g_acnt[m], 0) < 16) __nanosleep(128);
        }
        __syncthreads();
        gemm_body<false>(sbase, tid, attnh, wprojT, outp,
                         (size_t)m * 128, (size_t)n0, DM_N);
    }
}

// ---------------------------------------------------------------------------
extern "C" void kernel_launch(void* const* d_in, const int* in_sizes, int n_in,
                              void* d_out, int out_size)
{
    const float* x      = (const float*)d_in[0];   // (4, 2048, 1024)
    const float* w_qkv  = (const float*)d_in[1];   // (1024, 3072)
    const float* w_proj = (const float*)d_in[2];   // (1024, 1024)
    float* out          = (float*)d_out;           // (4, 2048, 1024)

    __half *qkvh, *attnh, *xh, *wqkvT, *wprojT;
    cudaGetSymbolAddress((void**)&qkvh, g_qkvh);
    cudaGetSymbolAddress((void**)&attnh, g_attnh);
    cudaGetSymbolAddress((void**)&xh, g_xh);
    cudaGetSymbolAddress((void**)&wqkvT, g_wqkvT);
    cudaGetSymbolAddress((void**)&wprojT, g_wprojT);

    cudaFuncSetAttribute(mega_kernel,
                         cudaFuncAttributeMaxDynamicSharedMemorySize, MEGA_SMEM);

    // 0) Prologue: x->half, weights transpose->half, zero counters
    prologue_kernel<<<NBX + NBQ + NBP + 1, 256>>>(x, w_qkv, w_proj,
                                                  xh, wqkvT, wprojT);

    // 1) Mega kernel: QKV -> attention -> proj, dataflow-ordered
    mega_kernel<<<NQKV + NATT + NPROJ, 256, MEGA_SMEM>>>(
        xh, wqkvT, wprojT, qkvh, attnh, out);
}